// round 4
// baseline (speedup 1.0000x reference)
#include <cuda_runtime.h>

// CostVolumeCorrelationLayer: B=8, H=W=128, C=128, maxDisp=4 -> 81 displacements
// out[b,y,x, dy*9+dx] = leaky_relu( mean_c( F1[b,y,x,c] * F2pad[b,y+dy,x+dx,c] ), 0.1 )
//
// Round-4: warp-specialized producer/consumer with double-buffered smem.
//  - 704 threads: warps 0..17 = compute (warp -> (row, dy)); warps 18..21 = fill.
//  - CCH=16 channels per chunk, 2 buffers; fill(k+1) overlaps compute(k).
//  - Named-barrier pipeline: FULL[buf] ids 1,2; EMPTY[buf] ids 3,4; count 704.
//  - smem rows: channel c=4cq+k -> row rho=k*4+cq, stride 136 floats (== 8 mod 32)
//    -> fill transpose-scatter STS.32 conflict-free; compute LDS.128 contiguous.

#define BB 8
#define HH 128
#define WW 128
#define CC_TOT 128
#define KDISP 81

#define CCH 16
#define NCHUNK (CC_TOT / CCH)       // 8
#define NCOMPUTE 576                // 18 warps
#define NFILL 128                   // 4 warps
#define NTHREADS (NCOMPUTE + NFILL) // 704
#define ROWS_PER_CTA 2
#define F2ROWS 10                   // row(0..1)+dy(0..8) -> 0..9

#define ROW_F4 34                   // 136 floats == 8 (mod 32) -> conflict-free fill
#define ROW_FLOATS (ROW_F4 * 4)     // 136
#define CH_ROW_F4 (CCH * ROW_F4)    // 544

#define F2T_F4 (F2ROWS * CH_ROW_F4)        // 5440 f4
#define F1T_F4 (ROWS_PER_CTA * CH_ROW_F4)  // 1088 f4
#define BUF_F4 (F2T_F4 + F1T_F4)           // 6528 f4 = 104448 B
#define SMEM_BYTES (2 * BUF_F4 * 16)       // 208896 B

using ull = unsigned long long;

__device__ __forceinline__ void ffma2(ull &acc, ull a, ull b) {
    asm("fma.rn.f32x2 %0, %1, %2, %0;" : "+l"(acc) : "l"(a), "l"(b));
}
__device__ __forceinline__ void bar_sync(int id) {
    asm volatile("bar.sync %0, %1;" :: "r"(id), "n"(NTHREADS) : "memory");
}
__device__ __forceinline__ void bar_arrive(int id) {
    asm volatile("bar.arrive %0, %1;" :: "r"(id), "n"(NTHREADS) : "memory");
}

__global__ __launch_bounds__(NTHREADS, 1)
void corr_kernel(const float* __restrict__ F1,
                 const float* __restrict__ F2,
                 float* __restrict__ out)
{
    extern __shared__ float4 smem4[];

    const int y0  = blockIdx.x * 2;
    const int b   = blockIdx.y;
    const int tid = threadIdx.x;
    const int w   = tid >> 5;
    const int g   = tid & 31;

    if (w >= 18) {
        // ================= PRODUCER (4 warps, 128 threads) =================
        const int ptid = tid - NCOMPUTE;   // 0..127
        for (int ck = 0; ck < NCHUNK; ck++) {
            const int buf = ck & 1;
            const int c0  = ck * CCH;
            if (ck >= 2) bar_sync(3 + buf);           // wait buffer consumed
            float* F2tf = reinterpret_cast<float*>(smem4 + (size_t)buf * BUF_F4);
            float* F1tf = F2tf + F2T_F4 * 4;

            // F2: 10 halo rows, xi=0..135 (x=xi-4), 4 channel-quads
#pragma unroll 4
            for (int q = ptid; q < F2ROWS * 136 * 4; q += NFILL) {
                int r   = q / 544;
                int rem = q - r * 544;
                int xi  = rem >> 2;
                int cq  = rem & 3;
                int x   = xi - 4;
                int yy  = y0 + r - 4;
                float4 val = make_float4(0.f, 0.f, 0.f, 0.f);
                if (yy >= 0 && yy < HH && x >= 0 && x < WW) {
                    val = __ldcg(reinterpret_cast<const float4*>(
                        F2 + (((size_t)(b * HH + yy) * WW + x) * CC_TOT + c0 + 4 * cq)));
                }
                float* base = F2tf + (size_t)r * (CCH * ROW_FLOATS);
                base[(0 * 4 + cq) * ROW_FLOATS + xi] = val.x;
                base[(1 * 4 + cq) * ROW_FLOATS + xi] = val.y;
                base[(2 * 4 + cq) * ROW_FLOATS + xi] = val.z;
                base[(3 * 4 + cq) * ROW_FLOATS + xi] = val.w;
            }
            // F1: 2 rows, xi=0..127
#pragma unroll 4
            for (int q = ptid; q < ROWS_PER_CTA * 128 * 4; q += NFILL) {
                int r2  = q >> 9;
                int rem = q & 511;
                int xi  = rem >> 2;
                int cq  = rem & 3;
                float4 val = __ldcg(reinterpret_cast<const float4*>(
                    F1 + (((size_t)(b * HH + y0 + r2) * WW + xi) * CC_TOT + c0 + 4 * cq)));
                float* base = F1tf + (size_t)r2 * (CCH * ROW_FLOATS);
                base[(0 * 4 + cq) * ROW_FLOATS + xi] = val.x;
                base[(1 * 4 + cq) * ROW_FLOATS + xi] = val.y;
                base[(2 * 4 + cq) * ROW_FLOATS + xi] = val.z;
                base[(3 * 4 + cq) * ROW_FLOATS + xi] = val.w;
            }
            bar_arrive(1 + buf);                      // buffer full
        }
    } else {
        // ================= CONSUMER (18 warps, 576 threads) =================
        const int row = (w >= 9) ? 1 : 0;
        const int dy  = w - 9 * row;

        ull acc[2][9];
#pragma unroll
        for (int i = 0; i < 2; i++)
#pragma unroll
            for (int dx = 0; dx < 9; dx++) acc[i][dx] = 0ull;

        for (int ck = 0; ck < NCHUNK; ck++) {
            const int buf = ck & 1;
            bar_sync(1 + buf);                        // wait buffer full

            const ulonglong2* bufp =
                reinterpret_cast<const ulonglong2*>(smem4 + (size_t)buf * BUF_F4);
            const ulonglong2* f2base = bufp + (size_t)(row + dy) * CH_ROW_F4;
            const ulonglong2* f1base = bufp + (size_t)F2T_F4 + (size_t)row * CH_ROW_F4;

#pragma unroll 4
            for (int cr = 0; cr < CCH; cr++) {
                ulonglong2 A  = f1base[(size_t)cr * ROW_F4 + g];       // px 4g..4g+3
                ulonglong2 V0 = f2base[(size_t)cr * ROW_F4 + g];       // px 4g-4..4g-1
                ulonglong2 V1 = f2base[(size_t)cr * ROW_F4 + g + 1];   // px 4g..4g+3
                ulonglong2 V2 = f2base[(size_t)cr * ROW_F4 + g + 2];   // px 4g+4..4g+7

                ull f1a = A.x, f1b = A.y;
                ull vp[6] = { V0.x, V0.y, V1.x, V1.y, V2.x, V2.y };

                ull m[5];
#pragma unroll
                for (int j = 0; j < 5; j++) {
                    unsigned int lo = (unsigned int)(vp[j] >> 32);
                    unsigned int hi = (unsigned int)(vp[j + 1]);
                    asm("mov.b64 %0, {%1,%2};" : "=l"(m[j]) : "r"(lo), "r"(hi));
                }
#pragma unroll
                for (int e = 0; e < 5; e++) {
                    ffma2(acc[0][2 * e], f1a, vp[e]);
                    ffma2(acc[1][2 * e], f1b, vp[e + 1]);
                }
#pragma unroll
                for (int o = 0; o < 4; o++) {
                    ffma2(acc[0][2 * o + 1], f1a, m[o]);
                    ffma2(acc[1][2 * o + 1], f1b, m[o + 1]);
                }
            }
            bar_arrive(3 + buf);                      // buffer consumed
        }

        // stage results (written below after full-block sync)
        __syncthreads();
        {
            float* ob = reinterpret_cast<float*>(smem4);   // reuse buffer 0 region
            const float inv = 1.0f / 128.0f;
#pragma unroll
            for (int i = 0; i < 2; i++) {
                int px = 4 * g + 2 * i;
#pragma unroll
                for (int dx = 0; dx < 9; dx++) {
                    ull a = acc[i][dx];
                    float v0 = __uint_as_float((unsigned int)a) * inv;
                    float v1 = __uint_as_float((unsigned int)(a >> 32)) * inv;
                    v0 = v0 > 0.f ? v0 : 0.1f * v0;
                    v1 = v1 > 0.f ? v1 : 0.1f * v1;
                    int k = dy * 9 + dx;
                    // two rows staged side by side: row r at offset r*WW*KDISP
                    ob[(size_t)row * WW * KDISP + px * KDISP + k]       = v0;
                    ob[(size_t)row * WW * KDISP + (px + 1) * KDISP + k] = v1;
                }
            }
        }
        goto epilogue_join;
    }

    // producers join here
    __syncthreads();
epilogue_join:
    __syncthreads();   // staging complete, everyone copies out

    {
        // 2 rows * 128 px * 81 = 20736 floats = 5184 float4, contiguous in gmem
        const float4* obv = reinterpret_cast<const float4*>(smem4);
        float4* ov = reinterpret_cast<float4*>(
            out + ((size_t)(b * HH + y0)) * WW * KDISP);
        for (int q = tid; q < (ROWS_PER_CTA * WW * KDISP) / 4; q += NTHREADS) {
            ov[q] = obv[q];
        }
    }
}

extern "C" void kernel_launch(void* const* d_in, const int* in_sizes, int n_in,
                              void* d_out, int out_size)
{
    const float* F1 = (const float*)d_in[0];
    const float* F2 = (const float*)d_in[1];
    float* out = (float*)d_out;

    cudaFuncSetAttribute(corr_kernel, cudaFuncAttributeMaxDynamicSharedMemorySize, SMEM_BYTES);

    dim3 grid(HH / ROWS_PER_CTA, BB);   // (y-pair, b): y-adjacent CTAs -> L2 reuse of F2 halo
    dim3 block(NTHREADS);
    corr_kernel<<<grid, block, SMEM_BYTES>>>(F1, F2, out);
}